// round 1
// baseline (speedup 1.0000x reference)
#include <cuda_runtime.h>
#include <math.h>

#define N_TOT 2048
#define T_SEQ 70
#define HID   230
#define DIN   60
#define EMB_W 50
#define NBAG  64
#define BAGSZ 32
#define NREL  100

// ---------------- scratch (device globals; no allocation allowed) ----------
__device__ float g_emb[(size_t)T_SEQ * N_TOT * DIN];          // time-major [t][n][60]
__device__ float g_h[2 * 2 * N_TOT * HID];                    // [buf][dir][n][j] double-buffered
__device__ float g_tup[(size_t)2 * T_SEQ * N_TOT * HID];      // [dir][t][n][j]
__device__ float g_repre[N_TOT * HID];
__device__ float g_sen_s[NBAG * HID];
__device__ float g_loss_part[NBAG];

// ---------------- packed f32x2 helpers -------------------------------------
__device__ __forceinline__ unsigned long long packw(float w) {
    unsigned long long r;
    asm("mov.b64 %0, {%1, %1};" : "=l"(r) : "f"(w));
    return r;
}
__device__ __forceinline__ void fma2(float2 &a, const float2 &x, unsigned long long w2) {
    asm("fma.rn.f32x2 %0, %1, %2, %0;"
        : "+l"(reinterpret_cast<unsigned long long &>(a))
        : "l"(reinterpret_cast<const unsigned long long &>(x)), "l"(w2));
}

// ---------------- init ------------------------------------------------------
__global__ void zero_h_kernel() {
    int i = blockIdx.x * blockDim.x + threadIdx.x;
    if (i < 2 * 2 * N_TOT * HID) g_h[i] = 0.f;
}

// ---------------- embedding gather (time-major) ----------------------------
__global__ void gather_kernel(const int *__restrict__ sent, const int *__restrict__ p1,
                              const int *__restrict__ p2, const float *__restrict__ wemb,
                              const float *__restrict__ p1t, const float *__restrict__ p2t) {
    size_t idx = (size_t)blockIdx.x * blockDim.x + threadIdx.x;
    if (idx >= (size_t)N_TOT * T_SEQ * DIN) return;
    int k = (int)(idx % DIN);
    size_t nt = idx / DIN;
    int t = (int)(nt % T_SEQ);
    int n = (int)(nt / T_SEQ);
    float v;
    if (k < EMB_W) {
        v = wemb[(size_t)sent[n * T_SEQ + t] * EMB_W + k];
    } else if (k < EMB_W + 5) {
        v = p1t[p1[n * T_SEQ + t] * 5 + (k - EMB_W)];
    } else {
        v = p2t[p2[n * T_SEQ + t] * 5 + (k - EMB_W - 5)];
    }
    g_emb[((size_t)t * N_TOT + n) * DIN + k] = v;
}

// ---------------- GRU step: fused [emb|h] x [Wih|Whh]^T + gates -------------
// grid: (16 Mtiles, 8 jtiles, 2 dirs), block 256 (tx=tid&15 -> j, ty=tid>>4 -> samples)
// tile: 128 samples x 32 hidden-j. Per thread: 8 samples (4 packed pairs) x 2 j.
#define GRU_KPHASE(Wp, Xp, Kv, XSTR, AN)                                            \
    {                                                                                \
        const float *W_ = (Wp);                                                      \
        const float *X_ = (Xp);                                                      \
        const int K_ = (Kv);                                                         \
        const int XS_ = (XSTR);                                                      \
        for (int k0 = 0; k0 < K_; k0 += 16) {                                        \
            _Pragma("unroll") for (int it = 0; it < 8; it++) {                       \
                int l = tid + it * 256;                                              \
                int rr = l >> 4, kk = l & 15;                                        \
                int k = k0 + kk;                                                     \
                Xs[kk][rr] = (k < K_) ? X_[(size_t)(n0 + rr) * XS_ + k] : 0.f;       \
            }                                                                        \
            _Pragma("unroll") for (int it = 0; it < 6; it++) {                       \
                int l = tid + it * 256;                                              \
                int c = l >> 4, kk = l & 15;                                         \
                int gate = c >> 5;                                                   \
                int j = j0 + (c & 31);                                               \
                int k = k0 + kk;                                                     \
                float w = 0.f;                                                       \
                if (j < HID && k < K_) w = W_[(size_t)(gate * HID + j) * K_ + k];    \
                Ws[kk][c] = w;                                                       \
            }                                                                        \
            __syncthreads();                                                         \
            _Pragma("unroll") for (int kk = 0; kk < 16; kk++) {                      \
                float2 xv[4];                                                        \
                _Pragma("unroll") for (int i = 0; i < 4; i++)                        \
                    xv[i] = *(const float2 *)&Xs[kk][ty * 2 + i * 32];               \
                _Pragma("unroll") for (int jj = 0; jj < 2; jj++) {                   \
                    int c = tx * 2 + jj;                                             \
                    unsigned long long wr2 = packw(Ws[kk][c]);                       \
                    unsigned long long wz2 = packw(Ws[kk][32 + c]);                  \
                    unsigned long long wn2 = packw(Ws[kk][64 + c]);                  \
                    _Pragma("unroll") for (int i = 0; i < 4; i++) {                  \
                        fma2(ar[i][jj], xv[i], wr2);                                 \
                        fma2(az[i][jj], xv[i], wz2);                                 \
                        fma2(AN[i][jj], xv[i], wn2);                                 \
                    }                                                                \
                }                                                                    \
            }                                                                        \
            __syncthreads();                                                         \
        }                                                                            \
    }

__global__ void __launch_bounds__(256, 2) gru_step_kernel(
    int s,
    const float *__restrict__ Wihf, const float *__restrict__ Whhf,
    const float *__restrict__ bihf, const float *__restrict__ bhhf,
    const float *__restrict__ Wihb, const float *__restrict__ Whhb,
    const float *__restrict__ bihb, const float *__restrict__ bhhb) {
    const int dir = blockIdx.z;
    const int t = (dir == 0) ? s : (T_SEQ - 1 - s);
    const float *Wih = dir ? Wihb : Wihf;
    const float *Whh = dir ? Whhb : Whhf;
    const float *bih = dir ? bihb : bihf;
    const float *bhh = dir ? bhhb : bhhf;

    const int n0 = blockIdx.x * 128;
    const int j0 = blockIdx.y * 32;
    const int tid = threadIdx.x;
    const int tx = tid & 15;
    const int ty = tid >> 4;

    const float *hin = g_h + (size_t)((s & 1) * 2 + dir) * N_TOT * HID;
    float *hout = g_h + (size_t)(((s + 1) & 1) * 2 + dir) * N_TOT * HID;

    __shared__ float Xs[16][130];
    __shared__ float Ws[16][97];

    float2 ar[4][2], az[4][2], an1[4][2], an2[4][2];
#pragma unroll
    for (int i = 0; i < 4; i++)
#pragma unroll
        for (int jj = 0; jj < 2; jj++) {
            ar[i][jj] = make_float2(0.f, 0.f);
            az[i][jj] = make_float2(0.f, 0.f);
            an1[i][jj] = make_float2(0.f, 0.f);
            an2[i][jj] = make_float2(0.f, 0.f);
        }

    // phase 1: x = emb_t  (K=60)   accumulates r, z, i_n
    GRU_KPHASE(Wih, g_emb + (size_t)t * N_TOT * DIN, DIN, DIN, an1);
    // phase 2: x = h_prev (K=230)  accumulates r, z, h_n
    GRU_KPHASE(Whh, hin, HID, HID, an2);

    // epilogue: gates + state update
#pragma unroll
    for (int jj = 0; jj < 2; jj++) {
        int j = j0 + tx * 2 + jj;
        if (j >= HID) continue;
        float br = bih[j] + bhh[j];
        float bz = bih[HID + j] + bhh[HID + j];
        float bi_n = bih[2 * HID + j];
        float bh_n = bhh[2 * HID + j];
#pragma unroll
        for (int i = 0; i < 4; i++) {
            int nb = n0 + ty * 2 + i * 32;
            float arv[2] = {ar[i][jj].x, ar[i][jj].y};
            float azv[2] = {az[i][jj].x, az[i][jj].y};
            float a1v[2] = {an1[i][jj].x, an1[i][jj].y};
            float a2v[2] = {an2[i][jj].x, an2[i][jj].y};
#pragma unroll
            for (int p = 0; p < 2; p++) {
                int n = nb + p;
                float r = 1.f / (1.f + expf(-(arv[p] + br)));
                float z = 1.f / (1.f + expf(-(azv[p] + bz)));
                float nn = tanhf(a1v[p] + bi_n + r * (a2v[p] + bh_n));
                float hold = hin[(size_t)n * HID + j];
                float hnew = (1.f - z) * nn + z * hold;
                hout[(size_t)n * HID + j] = hnew;
                g_tup[(((size_t)dir * T_SEQ + t) * N_TOT + n) * HID + j] = hnew;
            }
        }
    }
}

// ---------------- word-level attention (online softmax, single pass) -------
__global__ void __launch_bounds__(256) attn_kernel(const float *__restrict__ att_w) {
    const int n = blockIdx.x;
    const int tid = threadIdx.x;
    __shared__ float xsum[HID];
    __shared__ float red[8];
    __shared__ float s_bc;

    float acc = 0.f;
    float m = -1e30f, denom = 0.f;
    float w = (tid < HID) ? att_w[tid] : 0.f;

    for (int t = 0; t < T_SEQ; t++) {
        if (tid < HID) {
            size_t i0 = (((size_t)0 * T_SEQ + t) * N_TOT + n) * HID + tid;
            size_t i1 = (((size_t)1 * T_SEQ + t) * N_TOT + n) * HID + tid;
            xsum[tid] = g_tup[i0] + g_tup[i1];
        }
        __syncthreads();
        float part = (tid < HID) ? tanhf(xsum[tid]) * w : 0.f;
#pragma unroll
        for (int o = 16; o > 0; o >>= 1) part += __shfl_down_sync(0xffffffffu, part, o);
        if ((tid & 31) == 0) red[tid >> 5] = part;
        __syncthreads();
        if (tid == 0) {
            float sm = 0.f;
#pragma unroll
            for (int q = 0; q < 8; q++) sm += red[q];
            s_bc = sm;
        }
        __syncthreads();
        float st = s_bc;
        float mn = fmaxf(m, st);
        float c = expf(m - mn);
        float e = expf(st - mn);
        denom = denom * c + e;
        if (tid < HID) acc = acc * c + e * xsum[tid];
        m = mn;
        __syncthreads();
    }
    if (tid < HID) g_repre[n * HID + tid] = tanhf(acc / denom);
}

// ---------------- bag (sentence-level) attention ----------------------------
__global__ void __launch_bounds__(256) bag_kernel(const float *__restrict__ sen_a,
                                                  const float *__restrict__ sen_r) {
    const int b = blockIdx.x;
    const int tid = threadIdx.x;
    __shared__ float R[BAGSZ][HID];
    __shared__ float sv[BAGSZ];
    __shared__ float alpha[BAGSZ];

    for (int l = tid; l < BAGSZ * HID; l += 256) {
        int i = l / HID, j = l % HID;
        R[i][j] = g_repre[(b * BAGSZ + i) * HID + j];
    }
    __syncthreads();
    int wid = tid >> 5, lane = tid & 31;
    for (int i = wid; i < BAGSZ; i += 8) {
        float p = 0.f;
        for (int j = lane; j < HID; j += 32) p += R[i][j] * sen_a[j] * sen_r[j];
#pragma unroll
        for (int o = 16; o > 0; o >>= 1) p += __shfl_down_sync(0xffffffffu, p, o);
        if (lane == 0) sv[i] = p;
    }
    __syncthreads();
    if (tid == 0) {
        float mm = -1e30f;
        for (int i = 0; i < BAGSZ; i++) mm = fmaxf(mm, sv[i]);
        float ss = 0.f;
        for (int i = 0; i < BAGSZ; i++) {
            float e = expf(sv[i] - mm);
            alpha[i] = e;
            ss += e;
        }
        for (int i = 0; i < BAGSZ; i++) alpha[i] /= ss;
    }
    __syncthreads();
    for (int j = tid; j < HID; j += 256) {
        float a = 0.f;
#pragma unroll 4
        for (int i = 0; i < BAGSZ; i++) a += alpha[i] * R[i][j];
        g_sen_s[b * HID + j] = a;
    }
}

// ---------------- logits / prob / bce / acc ---------------------------------
__global__ void __launch_bounds__(128) logits_kernel(const float *__restrict__ rel,
                                                     const float *__restrict__ sen_d,
                                                     const float *__restrict__ y,
                                                     float *__restrict__ out) {
    const int b = blockIdx.x;
    const int tid = threadIdx.x;
    __shared__ float ss[HID];
    __shared__ float lg[NREL];
    __shared__ float mmax;
    __shared__ int amax;
    __shared__ float dsum;

    for (int j = tid; j < HID; j += 128) ss[j] = g_sen_s[b * HID + j];
    __syncthreads();
    if (tid < NREL) {
        float a = sen_d[tid];
        const float *row = rel + (size_t)tid * HID;
        for (int j = 0; j < HID; j++) a += ss[j] * row[j];
        lg[tid] = a;
    }
    __syncthreads();
    if (tid == 0) {
        float mm = lg[0];
        int am = 0;
        for (int c = 1; c < NREL; c++)
            if (lg[c] > mm) { mm = lg[c]; am = c; }
        mmax = mm;
        amax = am;
        float sum = 0.f;
        for (int c = 0; c < NREL; c++) sum += expf(lg[c] - mm);
        dsum = sum;
    }
    __syncthreads();
    if (tid < NREL) {
        out[1 + NBAG + b * NREL + tid] = expf(lg[tid] - mmax) / dsum;
    }
    if (tid == 0) {
        float loss = 0.f;
        int lab = 0;
        for (int c = 0; c < NREL; c++) {
            float l = lg[c];
            float yv = y[b * NREL + c];
            loss += fmaxf(l, 0.f) - l * yv + log1pf(expf(-fabsf(l)));
            if (yv > 0.5f) lab = c;
        }
        g_loss_part[b] = loss / (float)NREL;
        out[1 + b] = (amax == lab) ? 1.f : 0.f;
    }
}

__global__ void loss_sum_kernel(float *__restrict__ out) {
    if (threadIdx.x == 0) {
        float s = 0.f;
        for (int b = 0; b < NBAG; b++) s += g_loss_part[b];
        out[0] = s;
    }
}

// ---------------- launch -----------------------------------------------------
extern "C" void kernel_launch(void *const *d_in, const int *in_sizes, int n_in,
                              void *d_out, int out_size) {
    const int *sentence = (const int *)d_in[0];
    const int *pos1 = (const int *)d_in[1];
    const int *pos2 = (const int *)d_in[2];
    /* d_in[3] total_shape: bags are fixed size 32 (arange(65)*32) */
    const float *y_batch = (const float *)d_in[4];
    const float *word_emb = (const float *)d_in[5];
    const float *p1t = (const float *)d_in[6];
    const float *p2t = (const float *)d_in[7];
    const float *Wihf = (const float *)d_in[8];
    const float *Whhf = (const float *)d_in[9];
    const float *bihf = (const float *)d_in[10];
    const float *bhhf = (const float *)d_in[11];
    const float *Wihb = (const float *)d_in[12];
    const float *Whhb = (const float *)d_in[13];
    const float *bihb = (const float *)d_in[14];
    const float *bhhb = (const float *)d_in[15];
    const float *attw = (const float *)d_in[16];
    const float *sena = (const float *)d_in[17];
    const float *senr = (const float *)d_in[18];
    const float *rel = (const float *)d_in[19];
    const float *send = (const float *)d_in[20];
    float *out = (float *)d_out;

    zero_h_kernel<<<(2 * 2 * N_TOT * HID + 255) / 256, 256>>>();
    gather_kernel<<<(int)(((size_t)N_TOT * T_SEQ * DIN + 255) / 256), 256>>>(
        sentence, pos1, pos2, word_emb, p1t, p2t);

    dim3 grid(16, 8, 2);
    for (int s = 0; s < T_SEQ; s++) {
        gru_step_kernel<<<grid, 256>>>(s, Wihf, Whhf, bihf, bhhf, Wihb, Whhb, bihb, bhhb);
    }

    attn_kernel<<<N_TOT, 256>>>(attw);
    bag_kernel<<<NBAG, 256>>>(sena, senr);
    logits_kernel<<<NBAG, 128>>>(rel, send, y_batch, out);
    loss_sum_kernel<<<1, 32>>>(out);
}